// round 16
// baseline (speedup 1.0000x reference)
#include <cuda_runtime.h>
#include <cuda_fp16.h>

// Problem constants
constexpr int NB = 32;    // batch
constexpr int NT = 1024;  // tokens (32x32)
constexpr int NF = 768;   // features
constexpr int NC = NF / 128;                // 6 feature chunks (32 lanes x float4)
constexpr int NS = 32;    // splits per batch in pass C
constexpr int TPW = 4;    // tokens per warp (processed simultaneously)
constexpr int BLK_PER_BATCH_A = NT / 32;    // 32 kA blocks per batch

// Scratch (device globals — no allocations; counters self-reset per launch)
__device__ __half  g_xh[NB * NT * NF]; // fp16 shadow of x (50.3 MB, L2-friendly)
__device__ float4  g_meta[NB * NT];    // {rnorm, p1, tok.fw0, tok.fw1}
__device__ float   g_q[NB * NF];       // normalized argmax token per batch
__device__ float   g_d0[NB * NS];
__device__ float   g_d1[NB * NS];
__device__ float   g_u [NB * NS];
__device__ unsigned g_cntA[NB];
__device__ unsigned g_cntC;

__device__ __forceinline__ float dot4(float4 a, float4 b) {
    return a.x * b.x + a.y * b.y + a.z * b.z + a.w * b.w;
}

// ---------------------------------------------------------------------------
// Kernel A: 256 threads, warp processes 4 tokens simultaneously (chunk-major,
// 4 loads in flight per step). Computes ||tok||, tok.(w0-w1) -> p1, and
// tok.fc_final_w{0,1}; ALSO writes the fp16 shadow copy g_xh consumed by kC.
// Last-finishing block per batch does the argmax (first-max tiebreak,
// matches jnp.argmax) and writes q = tok[idx]*rnorm (fp32, from x).
// ---------------------------------------------------------------------------
__global__ __launch_bounds__(256) void kA(const float* __restrict__ x,
                                          const float* __restrict__ fc_w,
                                          const float* __restrict__ fc_b,
                                          const float* __restrict__ fc_final_w) {
    const int warp = threadIdx.x >> 5;
    const int lane = threadIdx.x & 31;
    const int g0 = blockIdx.x * 32 + warp * TPW; // first token of this warp
    const int b  = blockIdx.x / BLK_PER_BATCH_A; // batch of this block

    __shared__ float ws[3 * NF];                 // 9 KB: wd, fw0, fw1
    for (int i = threadIdx.x; i < NF; i += 256)
        ws[i] = fc_w[i] - fc_w[NF + i];          // wd = w0 - w1
    for (int i = threadIdx.x; i < 2 * NF; i += 256)
        ws[NF + i] = fc_final_w[i];
    __syncthreads();
    const float4* wd = reinterpret_cast<const float4*>(ws);
    const float4* f0 = reinterpret_cast<const float4*>(ws + NF);
    const float4* f1 = reinterpret_cast<const float4*>(ws + 2 * NF);

    const float4* tok0 = reinterpret_cast<const float4*>(x + (size_t)g0 * NF);
    uint2* xh0 = reinterpret_cast<uint2*>(g_xh + (size_t)g0 * NF);

    float nrm[TPW], d[TPW], e0[TPW], e1[TPW];
#pragma unroll
    for (int tt = 0; tt < TPW; tt++) { nrm[tt] = d[tt] = e0[tt] = e1[tt] = 0.f; }

#pragma unroll
    for (int i = 0; i < NC; i++) {
        const float4 a = wd[lane + 32 * i];
        const float4 p = f0[lane + 32 * i];
        const float4 q = f1[lane + 32 * i];
#pragma unroll
        for (int tt = 0; tt < TPW; tt++) {
            const float4 v = tok0[(size_t)tt * (NF / 4) + lane + 32 * i];
            nrm[tt] += dot4(v, v);
            d[tt]   += dot4(v, a);
            e0[tt]  += dot4(v, p);
            e1[tt]  += dot4(v, q);
            // fp16 shadow write (4 halves = 8B per lane, coalesced 256B/warp)
            const __half2 h01 = __floats2half2_rn(v.x, v.y);
            const __half2 h23 = __floats2half2_rn(v.z, v.w);
            uint2 hw;
            hw.x = *reinterpret_cast<const unsigned*>(&h01);
            hw.y = *reinterpret_cast<const unsigned*>(&h23);
            xh0[(size_t)tt * (NF / 4) + lane + 32 * i] = hw;
        }
    }
    // 16 independent butterflies, pipelined
#pragma unroll
    for (int o = 16; o; o >>= 1) {
#pragma unroll
        for (int tt = 0; tt < TPW; tt++) {
            nrm[tt] += __shfl_xor_sync(0xffffffffu, nrm[tt], o);
            d[tt]   += __shfl_xor_sync(0xffffffffu, d[tt], o);
            e0[tt]  += __shfl_xor_sync(0xffffffffu, e0[tt], o);
            e1[tt]  += __shfl_xor_sync(0xffffffffu, e1[tt], o);
        }
    }
    if (lane == 0) {
        const float bd = fc_b[0] - fc_b[1];
#pragma unroll
        for (int tt = 0; tt < TPW; tt++) {
            const float p1 = 1.f / (1.f + expf(d[tt] + bd));
            g_meta[g0 + tt] = make_float4(rsqrtf(nrm[tt]), p1, e0[tt], e1[tt]);
        }
    }
    __syncthreads();

    // Single release fence per block (syncthreads orders all block writes —
    // including the g_xh stores — before thread 0's gpu-scope fence+atomic).
    __shared__ unsigned s_last;
    if (threadIdx.x == 0) {
        __threadfence();
        s_last = atomicAdd(&g_cntA[b], 1u);
    }
    __syncthreads();
    if (s_last != BLK_PER_BATCH_A - 1) return;
    __threadfence();  // acquire: see all blocks' meta writes

    // argmax over 1024 p1 values, 256 threads x 4 candidates.
    // Comparator (v>best)||(v==best && i<besti) => global first-max.
    float bestv = -1.f; int besti = 0;
#pragma unroll
    for (int k = 0; k < 4; k++) {
        const int t = threadIdx.x + 256 * k;
        const float v = g_meta[b * NT + t].y;
        if (v > bestv || (v == bestv && t < besti)) { bestv = v; besti = t; }
    }
#pragma unroll
    for (int o = 16; o; o >>= 1) {
        float v2 = __shfl_xor_sync(0xffffffffu, bestv, o);
        int   i2 = __shfl_xor_sync(0xffffffffu, besti, o);
        if (v2 > bestv || (v2 == bestv && i2 < besti)) { bestv = v2; besti = i2; }
    }
    __shared__ float swv[8];
    __shared__ int   swi[8];
    if (lane == 0) { swv[warp] = bestv; swi[warp] = besti; }
    __syncthreads();
    __shared__ int s_idx;
    if (threadIdx.x == 0) {
        float bv = swv[0]; int bi = swi[0];
#pragma unroll
        for (int w = 1; w < 8; w++)
            if (swv[w] > bv || (swv[w] == bv && swi[w] < bi)) { bv = swv[w]; bi = swi[w]; }
        s_idx = bi;
        g_cntA[b] = 0;  // reset for next graph replay
    }
    __syncthreads();
    const int idx = s_idx;
    const float rn = g_meta[b * NT + idx].x;
    const float* qt = x + ((size_t)b * NT + idx) * NF;  // q from fp32 x
    for (int f = threadIdx.x; f < NF; f += 256)
        g_q[b * NF + f] = qt[f] * rn;
}

// ---------------------------------------------------------------------------
// Kernel C: streaming scoring pass over the fp16 shadow (HALF the bytes).
// grid = (NS, NB), 256 threads, warp handles 4 tokens chunk-major.
// Blocks consume tokens in REVERSE global order so the L2-resident tail of
// g_xh (most recently written by kA) is hit first.
// Last-finishing block of the grid reduces all splits and writes output.
// ---------------------------------------------------------------------------
__global__ __launch_bounds__(256) void kC(const float* __restrict__ fc_final_b,
                                          float* __restrict__ out) {
    // Reverse block mapping: linear rank -> token-block from the end.
    const int lin  = blockIdx.x + NS * blockIdx.y;
    const int rlin = NB * NS - 1 - lin;
    const int b    = rlin / NS;
    const int sp   = rlin % NS;
    const int warp = threadIdx.x >> 5;
    const int lane = threadIdx.x & 31;

    __shared__ float4 q4s[NF / 4];     // 3 KB
    __shared__ float  s0[8], s1[8], su[8];

    const float4* q4 = reinterpret_cast<const float4*>(g_q + b * NF);
    for (int i = threadIdx.x; i < NF / 4; i += 256) q4s[i] = q4[i];
    __syncthreads();

    const int t0 = sp * 32 + warp * TPW;

    // Prefetch 4 metas (independent broadcast loads)
    float4 m[TPW];
#pragma unroll
    for (int tt = 0; tt < TPW; tt++)
        m[tt] = g_meta[b * NT + t0 + tt];

    const uint2* tok0 = reinterpret_cast<const uint2*>(g_xh + ((size_t)b * NT + t0) * NF);

    float s[TPW];
#pragma unroll
    for (int tt = 0; tt < TPW; tt++) s[tt] = 0.f;

#pragma unroll
    for (int i = 0; i < NC; i++) {
        const float4 q = q4s[lane + 32 * i];
#pragma unroll
        for (int tt = 0; tt < TPW; tt++) {
            const uint2 hw = tok0[(size_t)tt * (NF / 4) + lane + 32 * i];
            const float2 v01 = __half22float2(*reinterpret_cast<const __half2*>(&hw.x));
            const float2 v23 = __half22float2(*reinterpret_cast<const __half2*>(&hw.y));
            s[tt] += v01.x * q.x + v01.y * q.y + v23.x * q.z + v23.y * q.w;
        }
    }
    // 4 independent butterflies
#pragma unroll
    for (int o = 16; o; o >>= 1) {
#pragma unroll
        for (int tt = 0; tt < TPW; tt++)
            s[tt] += __shfl_xor_sync(0xffffffffu, s[tt], o);
    }
    float U = 0.f, D0 = 0.f, D1 = 0.f;
#pragma unroll
    for (int tt = 0; tt < TPW; tt++) {
        const float u = expf(s[tt] * m[tt].x) * m[tt].y;  // lane-replicated
        U  += u;
        D0 += u * m[tt].z;
        D1 += u * m[tt].w;
    }

    // U/D0/D1 are lane-replicated: take lane 0's values only (no shuffle!).
    if (lane == 0) { s0[warp] = D0; s1[warp] = D1; su[warp] = U; }
    __syncthreads();

    __shared__ unsigned s_last;
    if (threadIdx.x == 0) {
        float A0 = 0.f, A1 = 0.f, AU = 0.f;
#pragma unroll
        for (int w = 0; w < 8; w++) { A0 += s0[w]; A1 += s1[w]; AU += su[w]; }
        g_d0[b * NS + sp] = A0;
        g_d1[b * NS + sp] = A1;
        g_u [b * NS + sp] = AU;
        __threadfence();
        s_last = atomicAdd(&g_cntC, 1u);
    }
    __syncthreads();
    if (s_last != (unsigned)(NB * NS - 1)) return;
    __threadfence();  // acquire all blocks' partials

    // Final reduce: threads 0..31 each own one batch; fixed summation order.
    if (threadIdx.x < NB) {
        const int bb = threadIdx.x;
        float A0 = 0.f, A1 = 0.f, AU = 0.f;
#pragma unroll
        for (int ss = 0; ss < NS; ss++) {
            A0 += g_d0[bb * NS + ss];
            A1 += g_d1[bb * NS + ss];
            AU += g_u [bb * NS + ss];
        }
        const float invU = 1.f / AU;
        out[bb * 2 + 0] = A0 * invU + fc_final_b[0];
        out[bb * 2 + 1] = A1 * invU + fc_final_b[1];
    }
    if (threadIdx.x == 0) g_cntC = 0;  // reset for next replay
}

// ---------------------------------------------------------------------------
extern "C" void kernel_launch(void* const* d_in, const int* in_sizes, int n_in,
                              void* d_out, int out_size) {
    const float* x          = (const float*)d_in[0];
    const float* fc_w       = (const float*)d_in[1];
    const float* fc_b       = (const float*)d_in[2];
    const float* fc_final_w = (const float*)d_in[3];
    const float* fc_final_b = (const float*)d_in[4];
    float* out = (float*)d_out;

    kA<<<NB * NT / 32, 256>>>(x, fc_w, fc_b, fc_final_w);
    dim3 gridC(NS, NB);
    kC<<<gridC, 256>>>(fc_final_b, out);
}

// round 17
// speedup vs baseline: 1.2097x; 1.2097x over previous
#include <cuda_runtime.h>

// Problem constants
constexpr int NB = 32;    // batch
constexpr int NT = 1024;  // tokens (32x32)
constexpr int NF = 768;   // features
constexpr int NC = NF / 128;                // 6 feature chunks (32 lanes x float4)
constexpr int NS = 16;    // splits per batch in pass C
constexpr int TPW_A = 4;  // tokens per warp in kA
constexpr int TPW_C = 8;  // tokens per warp in kC (high MLP)
constexpr int BLK_PER_BATCH_A = NT / 32;    // 32 kA blocks per batch

// Scratch (device globals — no allocations; counters self-reset per launch)
__device__ float4  g_meta[NB * NT];    // {rnorm, p1, tok.fw0, tok.fw1}
__device__ float   g_q[NB * NF];       // normalized argmax token per batch
__device__ float   g_d0[NB * NS];
__device__ float   g_d1[NB * NS];
__device__ float   g_u [NB * NS];
__device__ unsigned g_cntA[NB];
__device__ unsigned g_cntC;

__device__ __forceinline__ float dot4(float4 a, float4 b) {
    return a.x * b.x + a.y * b.y + a.z * b.z + a.w * b.w;
}

// ---------------------------------------------------------------------------
// Kernel A (R15-proven, ~7.5 TB/s): 256 threads, warp processes 4 tokens
// simultaneously (chunk-major). Computes ||tok||, tok.(w0-w1) -> p1, and
// tok.fc_final_w{0,1}, packed into one float4 per token. Last-finishing
// block per batch does the argmax (first-max tiebreak, matches jnp.argmax)
// and writes q = tok[idx]*rnorm.
// ---------------------------------------------------------------------------
__global__ __launch_bounds__(256) void kA(const float* __restrict__ x,
                                          const float* __restrict__ fc_w,
                                          const float* __restrict__ fc_b,
                                          const float* __restrict__ fc_final_w) {
    const int warp = threadIdx.x >> 5;
    const int lane = threadIdx.x & 31;
    const int g0 = blockIdx.x * 32 + warp * TPW_A; // first token of this warp
    const int b  = blockIdx.x / BLK_PER_BATCH_A;   // batch of this block

    __shared__ float ws[3 * NF];                   // 9 KB: wd, fw0, fw1
    for (int i = threadIdx.x; i < NF; i += 256)
        ws[i] = fc_w[i] - fc_w[NF + i];            // wd = w0 - w1
    for (int i = threadIdx.x; i < 2 * NF; i += 256)
        ws[NF + i] = fc_final_w[i];
    __syncthreads();
    const float4* wd = reinterpret_cast<const float4*>(ws);
    const float4* f0 = reinterpret_cast<const float4*>(ws + NF);
    const float4* f1 = reinterpret_cast<const float4*>(ws + 2 * NF);

    const float4* tok0 = reinterpret_cast<const float4*>(x + (size_t)g0 * NF);

    float nrm[TPW_A], d[TPW_A], e0[TPW_A], e1[TPW_A];
#pragma unroll
    for (int tt = 0; tt < TPW_A; tt++) { nrm[tt] = d[tt] = e0[tt] = e1[tt] = 0.f; }

#pragma unroll
    for (int i = 0; i < NC; i++) {
        const float4 a = wd[lane + 32 * i];
        const float4 p = f0[lane + 32 * i];
        const float4 q = f1[lane + 32 * i];
#pragma unroll
        for (int tt = 0; tt < TPW_A; tt++) {
            const float4 v = tok0[(size_t)tt * (NF / 4) + lane + 32 * i];
            nrm[tt] += dot4(v, v);
            d[tt]   += dot4(v, a);
            e0[tt]  += dot4(v, p);
            e1[tt]  += dot4(v, q);
        }
    }
    // 16 independent butterflies, pipelined
#pragma unroll
    for (int o = 16; o; o >>= 1) {
#pragma unroll
        for (int tt = 0; tt < TPW_A; tt++) {
            nrm[tt] += __shfl_xor_sync(0xffffffffu, nrm[tt], o);
            d[tt]   += __shfl_xor_sync(0xffffffffu, d[tt], o);
            e0[tt]  += __shfl_xor_sync(0xffffffffu, e0[tt], o);
            e1[tt]  += __shfl_xor_sync(0xffffffffu, e1[tt], o);
        }
    }
    if (lane == 0) {
        const float bd = fc_b[0] - fc_b[1];
#pragma unroll
        for (int tt = 0; tt < TPW_A; tt++) {
            const float p1 = 1.f / (1.f + __expf(d[tt] + bd));
            g_meta[g0 + tt] = make_float4(rsqrtf(nrm[tt]), p1, e0[tt], e1[tt]);
        }
    }
    __syncthreads();

    // Single release fence per block (syncthreads orders all block writes
    // before thread 0's gpu-scope fence + atomic).
    __shared__ unsigned s_last;
    if (threadIdx.x == 0) {
        __threadfence();
        s_last = atomicAdd(&g_cntA[b], 1u);
    }
    __syncthreads();
    if (s_last != BLK_PER_BATCH_A - 1) return;
    __threadfence();  // acquire: see all blocks' meta writes

    // argmax over 1024 p1 values, 256 threads x 4 candidates.
    // Comparator (v>best)||(v==best && i<besti) => global first-max.
    float bestv = -1.f; int besti = 0;
#pragma unroll
    for (int k = 0; k < 4; k++) {
        const int t = threadIdx.x + 256 * k;
        const float v = g_meta[b * NT + t].y;
        if (v > bestv || (v == bestv && t < besti)) { bestv = v; besti = t; }
    }
#pragma unroll
    for (int o = 16; o; o >>= 1) {
        float v2 = __shfl_xor_sync(0xffffffffu, bestv, o);
        int   i2 = __shfl_xor_sync(0xffffffffu, besti, o);
        if (v2 > bestv || (v2 == bestv && i2 < besti)) { bestv = v2; besti = i2; }
    }
    __shared__ float swv[8];
    __shared__ int   swi[8];
    if (lane == 0) { swv[warp] = bestv; swi[warp] = besti; }
    __syncthreads();
    __shared__ int s_idx;
    if (threadIdx.x == 0) {
        float bv = swv[0]; int bi = swi[0];
#pragma unroll
        for (int w = 1; w < 8; w++)
            if (swv[w] > bv || (swv[w] == bv && swi[w] < bi)) { bv = swv[w]; bi = swi[w]; }
        s_idx = bi;
        g_cntA[b] = 0;  // reset for next graph replay
    }
    __syncthreads();
    const int idx = s_idx;
    const float rn = g_meta[b * NT + idx].x;
    const float* qt = x + ((size_t)b * NT + idx) * NF;
    for (int f = threadIdx.x; f < NF; f += 256)
        g_q[b * NF + f] = qt[f] * rn;
}

// ---------------------------------------------------------------------------
// Kernel C: streaming scoring pass, fp32 x. grid = (NS, NB) = 512 blocks,
// 256 threads. Each warp processes EIGHT tokens simultaneously (chunk-major):
// 8 independent 16B loads per chunk step -> ~64 loads in flight per
// scheduler, covering DRAM latency. Butterfly/exp tail batched over 8
// independent chains. Last-finishing block reduces all splits -> output.
// ---------------------------------------------------------------------------
__global__ __launch_bounds__(256) void kC(const float* __restrict__ x,
                                          const float* __restrict__ fc_final_b,
                                          float* __restrict__ out) {
    const int b    = blockIdx.y;
    const int sp   = blockIdx.x;
    const int warp = threadIdx.x >> 5;
    const int lane = threadIdx.x & 31;

    __shared__ float4 q4s[NF / 4];     // 3 KB
    __shared__ float  s0[8], s1[8], su[8];

    const float4* q4 = reinterpret_cast<const float4*>(g_q + b * NF);
    for (int i = threadIdx.x; i < NF / 4; i += 256) q4s[i] = q4[i];
    __syncthreads();

    const int t0 = sp * (NT / NS) + warp * TPW_C;

    // Prefetch 8 metas (independent broadcast loads)
    float4 m[TPW_C];
#pragma unroll
    for (int tt = 0; tt < TPW_C; tt++)
        m[tt] = g_meta[b * NT + t0 + tt];

    const float4* tok0 = reinterpret_cast<const float4*>(x + ((size_t)b * NT + t0) * NF);

    float s[TPW_C];
#pragma unroll
    for (int tt = 0; tt < TPW_C; tt++) s[tt] = 0.f;

#pragma unroll
    for (int i = 0; i < NC; i++) {
        const float4 q = q4s[lane + 32 * i];
#pragma unroll
        for (int tt = 0; tt < TPW_C; tt++) {
            const float4 v = tok0[(size_t)tt * (NF / 4) + lane + 32 * i];
            s[tt] += dot4(v, q);
        }
    }
    // 8 independent butterflies
#pragma unroll
    for (int o = 16; o; o >>= 1) {
#pragma unroll
        for (int tt = 0; tt < TPW_C; tt++)
            s[tt] += __shfl_xor_sync(0xffffffffu, s[tt], o);
    }
    float U = 0.f, D0 = 0.f, D1 = 0.f;
#pragma unroll
    for (int tt = 0; tt < TPW_C; tt++) {
        const float u = __expf(s[tt] * m[tt].x) * m[tt].y;  // lane-replicated
        U  += u;
        D0 += u * m[tt].z;
        D1 += u * m[tt].w;
    }

    // U/D0/D1 are lane-replicated: take lane 0's values only (no shuffle!).
    if (lane == 0) { s0[warp] = D0; s1[warp] = D1; su[warp] = U; }
    __syncthreads();

    __shared__ unsigned s_last;
    if (threadIdx.x == 0) {
        float A0 = 0.f, A1 = 0.f, AU = 0.f;
#pragma unroll
        for (int w = 0; w < 8; w++) { A0 += s0[w]; A1 += s1[w]; AU += su[w]; }
        g_d0[b * NS + sp] = A0;
        g_d1[b * NS + sp] = A1;
        g_u [b * NS + sp] = AU;
        __threadfence();
        s_last = atomicAdd(&g_cntC, 1u);
    }
    __syncthreads();
    if (s_last != (unsigned)(NB * NS - 1)) return;
    __threadfence();  // acquire all blocks' partials

    // Final reduce: threads 0..31 each own one batch; fixed summation order.
    if (threadIdx.x < NB) {
        const int bb = threadIdx.x;
        float A0 = 0.f, A1 = 0.f, AU = 0.f;
#pragma unroll
        for (int ss = 0; ss < NS; ss++) {
            A0 += g_d0[bb * NS + ss];
            A1 += g_d1[bb * NS + ss];
            AU += g_u [bb * NS + ss];
        }
        const float invU = 1.f / AU;
        out[bb * 2 + 0] = A0 * invU + fc_final_b[0];
        out[bb * 2 + 1] = A1 * invU + fc_final_b[1];
    }
    if (threadIdx.x == 0) g_cntC = 0;  // reset for next replay
}

// ---------------------------------------------------------------------------
extern "C" void kernel_launch(void* const* d_in, const int* in_sizes, int n_in,
                              void* d_out, int out_size) {
    const float* x          = (const float*)d_in[0];
    const float* fc_w       = (const float*)d_in[1];
    const float* fc_b       = (const float*)d_in[2];
    const float* fc_final_w = (const float*)d_in[3];
    const float* fc_final_b = (const float*)d_in[4];
    float* out = (float*)d_out;

    kA<<<NB * NT / 32, 256>>>(x, fc_w, fc_b, fc_final_w);
    dim3 gridC(NS, NB);
    kC<<<gridC, 256>>>(x, fc_final_b, out);
}